// round 1
// baseline (speedup 1.0000x reference)
#include <cuda_runtime.h>
#include <math.h>

#define Nn   50000
#define Ee   600000
#define FA   78
#define Dd   128
#define Hh   8
#define EDd  12
#define Ll   4
#define Bb   512
#define DFFd 512

// ---------------- scratch (device globals; no runtime allocation) ----------------
__device__ float    g_h[(size_t)Nn * Dd];          // 25.6 MB  node features
__device__ float    g_qkvs[(size_t)Nn * 4 * Dd];   // 102.4 MB q|k|v|xr packed per row
__device__ float    g_ff[(size_t)Nn * DFFd];       // 102.4 MB FF hidden
__device__ float    g_agg[(size_t)Nn * Dd];        // 25.6 MB  message accumulator / ff2 out
__device__ float    g_alpha[(size_t)Ee * Hh];      // 19.2 MB  attention logits
__device__ unsigned g_mkey[Nn * Hh];               // per-(dst,head) max key
__device__ float    g_den[Nn * Hh];                // softmax denominators
__device__ float    g_packW[Dd * 4 * Dd];          // packed [Wq|Wk|Wv|Wskip] for layer
__device__ float    g_packb[4 * Dd];
__device__ float    g_pool[Bb * Dd];
__device__ float    g_cnt[Bb];

// monotone float <-> uint key (for atomicMax on float via unsigned)
__device__ __forceinline__ unsigned f2key(float f) {
    unsigned u = __float_as_uint(f);
    return (u & 0x80000000u) ? ~u : (u | 0x80000000u);
}
__device__ __forceinline__ float key2f(unsigned k) {
    unsigned u = (k & 0x80000000u) ? (k ^ 0x80000000u) : ~k;
    return __uint_as_float(u);
}

// ---------------- generic tiled fp32 GEMM: C = A[M,K] @ B[K,N] + bias, opt ReLU --------
template <bool RELU>
__global__ void __launch_bounds__(256) gemm_bias_k(
    const float* __restrict__ A, const float* __restrict__ B,
    const float* __restrict__ bias, float* __restrict__ C,
    int M, int N, int K)
{
    __shared__ __align__(16) float As[16][132];  // [k][m], padded
    __shared__ __align__(16) float Bs[16][128];  // [k][n]
    const int tid = threadIdx.x;
    const int bm = blockIdx.y * 128;
    const int bn = blockIdx.x * 128;
    const int tx = tid & 15;
    const int ty = tid >> 4;
    const int arow = tid >> 1;
    const int ak0  = (tid & 1) * 8;
    const int bcol = (tid & 31) * 4;
    const int bk   = tid >> 5;

    float acc[8][8];
#pragma unroll
    for (int i = 0; i < 8; i++)
#pragma unroll
        for (int j = 0; j < 8; j++) acc[i][j] = 0.f;

    for (int k0 = 0; k0 < K; k0 += 16) {
        // A tile (zero-padded at edges)
        {
            const int r = bm + arow;
#pragma unroll
            for (int kk = 0; kk < 8; kk++) {
                int k = k0 + ak0 + kk;
                float v = 0.f;
                if (r < M && k < K) v = A[(size_t)r * K + k];
                As[ak0 + kk][arow] = v;
            }
        }
        // B tile
#pragma unroll
        for (int it = 0; it < 2; it++) {
            int k = k0 + bk + it * 8;
            float4 v = make_float4(0.f, 0.f, 0.f, 0.f);
            if (k < K) v = *(const float4*)&B[(size_t)k * N + bn + bcol];
            *(float4*)&Bs[bk + it * 8][bcol] = v;
        }
        __syncthreads();
#pragma unroll
        for (int k = 0; k < 16; k++) {
            float a[8], b[8];
            *(float4*)&a[0] = *(const float4*)&As[k][ty * 8];
            *(float4*)&a[4] = *(const float4*)&As[k][ty * 8 + 4];
            *(float4*)&b[0] = *(const float4*)&Bs[k][tx * 8];
            *(float4*)&b[4] = *(const float4*)&Bs[k][tx * 8 + 4];
#pragma unroll
            for (int i = 0; i < 8; i++)
#pragma unroll
                for (int j = 0; j < 8; j++) acc[i][j] += a[i] * b[j];
        }
        __syncthreads();
    }
    float bv[8];
    *(float4*)&bv[0] = *(const float4*)&bias[bn + tx * 8];
    *(float4*)&bv[4] = *(const float4*)&bias[bn + tx * 8 + 4];
#pragma unroll
    for (int i = 0; i < 8; i++) {
        int r = bm + ty * 8 + i;
        if (r >= M) break;
        float out[8];
#pragma unroll
        for (int j = 0; j < 8; j++) {
            float v = acc[i][j] + bv[j];
            if (RELU) v = fmaxf(v, 0.f);
            out[j] = v;
        }
        *(float4*)&C[(size_t)r * N + bn + tx * 8]     = *(float4*)&out[0];
        *(float4*)&C[(size_t)r * N + bn + tx * 8 + 4] = *(float4*)&out[4];
    }
}

// ---------------- pack [Wq|Wk|Wv|Wskip] for one layer ----------------
__global__ void pack_qkvs_k(
    const float* __restrict__ Wq, const float* __restrict__ Wk,
    const float* __restrict__ Wv, const float* __restrict__ Ws,
    const float* __restrict__ bq, const float* __restrict__ bk,
    const float* __restrict__ bv, const float* __restrict__ bs, int l)
{
    int idx = blockIdx.x * 256 + threadIdx.x;
    if (idx < Dd * 4 * Dd) {
        int k = idx >> 9, col = idx & 511, s = col >> 7, j = col & 127;
        const float* W = (s == 0) ? Wq : (s == 1) ? Wk : (s == 2) ? Wv : Ws;
        g_packW[idx] = W[(size_t)l * Dd * Dd + k * Dd + j];
    }
    if (idx < 4 * Dd) {
        int s = idx >> 7, j = idx & 127;
        const float* bb = (s == 0) ? bq : (s == 1) ? bk : (s == 2) ? bv : bs;
        g_packb[idx] = bb[l * Dd + j];
    }
}

// ---------------- zero per-layer edge state ----------------
__global__ void zero_layer_k()
{
    int i = blockIdx.x * blockDim.x + threadIdx.x;
    int st = gridDim.x * blockDim.x;
    for (int j = i; j < Nn * Hh; j += st) { g_mkey[j] = 0u; g_den[j] = 0.f; }
    for (int j = i; j < Nn * Dd; j += st) g_agg[j] = 0.f;
}

// ---------------- edge pass 1: alpha + segment max ----------------
__global__ void __launch_bounds__(256) edge_pass1_k(
    const int* __restrict__ ei, const float* __restrict__ ea,
    const float* __restrict__ We, const float* __restrict__ be)
{
    __shared__ float sWe[EDd * Dd];
    __shared__ float sbe[Dd];
    for (int i = threadIdx.x; i < EDd * Dd; i += 256) sWe[i] = We[i];
    for (int i = threadIdx.x; i < Dd; i += 256) sbe[i] = be[i];
    __syncthreads();
    int warp = threadIdx.x >> 5, lane = threadIdx.x & 31;
    int eid = blockIdx.x * 8 + warp;
    if (eid >= Ee) return;
    int src = ei[eid], dst = ei[Ee + eid];
    float eav = (lane < EDd) ? ea[(size_t)eid * EDd + lane] : 0.f;
    int ch = lane * 4;
    float e0 = sbe[ch], e1 = sbe[ch + 1], e2 = sbe[ch + 2], e3 = sbe[ch + 3];
#pragma unroll
    for (int t = 0; t < EDd; t++) {
        float a = __shfl_sync(0xffffffffu, eav, t);
        e0 += a * sWe[t * Dd + ch + 0];
        e1 += a * sWe[t * Dd + ch + 1];
        e2 += a * sWe[t * Dd + ch + 2];
        e3 += a * sWe[t * Dd + ch + 3];
    }
    float4 qd = *(const float4*)&g_qkvs[(size_t)dst * 512 + ch];
    float4 ks = *(const float4*)&g_qkvs[(size_t)src * 512 + 128 + ch];
    float p = qd.x * (ks.x + e0) + qd.y * (ks.y + e1) +
              qd.z * (ks.z + e2) + qd.w * (ks.w + e3);
    p += __shfl_xor_sync(0xffffffffu, p, 1);
    p += __shfl_xor_sync(0xffffffffu, p, 2);
    if ((lane & 3) == 0) {
        float alpha = p * 0.25f;                 // SCALE = 1/sqrt(16)
        int h = lane >> 2;
        g_alpha[(size_t)eid * Hh + h] = alpha;
        atomicMax(&g_mkey[dst * Hh + h], f2key(alpha));
    }
}

// ---------------- edge pass 2: exp, denominator, message accumulation -------------
__global__ void __launch_bounds__(256) edge_pass2_k(
    const int* __restrict__ ei, const float* __restrict__ ea,
    const float* __restrict__ We, const float* __restrict__ be)
{
    __shared__ float sWe[EDd * Dd];
    __shared__ float sbe[Dd];
    for (int i = threadIdx.x; i < EDd * Dd; i += 256) sWe[i] = We[i];
    for (int i = threadIdx.x; i < Dd; i += 256) sbe[i] = be[i];
    __syncthreads();
    int warp = threadIdx.x >> 5, lane = threadIdx.x & 31;
    int eid = blockIdx.x * 8 + warp;
    if (eid >= Ee) return;
    int src = ei[eid], dst = ei[Ee + eid];
    float eav = (lane < EDd) ? ea[(size_t)eid * EDd + lane] : 0.f;
    int ch = lane * 4;
    float e0 = sbe[ch], e1 = sbe[ch + 1], e2 = sbe[ch + 2], e3 = sbe[ch + 3];
#pragma unroll
    for (int t = 0; t < EDd; t++) {
        float a = __shfl_sync(0xffffffffu, eav, t);
        e0 += a * sWe[t * Dd + ch + 0];
        e1 += a * sWe[t * Dd + ch + 1];
        e2 += a * sWe[t * Dd + ch + 2];
        e3 += a * sWe[t * Dd + ch + 3];
    }
    int h = lane >> 2;
    float m = key2f(g_mkey[dst * Hh + h]);
    float alpha = g_alpha[(size_t)eid * Hh + h];
    float ex = expf(alpha - m);
    if ((lane & 3) == 0) atomicAdd(&g_den[dst * Hh + h], ex);
    float4 vs = *(const float4*)&g_qkvs[(size_t)src * 512 + 256 + ch];
    float m0 = (vs.x + e0) * ex, m1 = (vs.y + e1) * ex;
    float m2 = (vs.z + e2) * ex, m3 = (vs.w + e3) * ex;
    float* dp = &g_agg[(size_t)dst * Dd + ch];
    asm volatile("red.global.add.v4.f32 [%0], {%1,%2,%3,%4};"
                 :: "l"(dp), "f"(m0), "f"(m1), "f"(m2), "f"(m3) : "memory");
}

// ---------------- node: normalize agg, beta gate, residual, LN1 ----------------
__global__ void __launch_bounds__(256) node_gate_ln1_k(
    const float* __restrict__ wb, const float* __restrict__ g1,
    const float* __restrict__ b1)
{
    int warp = threadIdx.x >> 5, lane = threadIdx.x & 31;
    int n = blockIdx.x * 8 + warp;
    if (n >= Nn) return;
    int ch = lane * 4;
    float4 ag = *(const float4*)&g_agg[(size_t)n * Dd + ch];
    float den = g_den[n * Hh + (lane >> 2)] + 1e-16f;
    float inv = 1.f / den;
    ag.x *= inv; ag.y *= inv; ag.z *= inv; ag.w *= inv;
    float4 xr = *(const float4*)&g_qkvs[(size_t)n * 512 + 384 + ch];
    float s =
        ag.x * wb[ch] + ag.y * wb[ch + 1] + ag.z * wb[ch + 2] + ag.w * wb[ch + 3] +
        xr.x * wb[128 + ch] + xr.y * wb[128 + ch + 1] + xr.z * wb[128 + ch + 2] + xr.w * wb[128 + ch + 3] +
        (ag.x - xr.x) * wb[256 + ch] + (ag.y - xr.y) * wb[256 + ch + 1] +
        (ag.z - xr.z) * wb[256 + ch + 2] + (ag.w - xr.w) * wb[256 + ch + 3];
#pragma unroll
    for (int o = 16; o; o >>= 1) s += __shfl_xor_sync(0xffffffffu, s, o);
    float beta = 1.f / (1.f + expf(-s));
    float4 hp = *(const float4*)&g_h[(size_t)n * Dd + ch];
    float t0 = beta * xr.x + (1.f - beta) * ag.x + hp.x;
    float t1 = beta * xr.y + (1.f - beta) * ag.y + hp.y;
    float t2 = beta * xr.z + (1.f - beta) * ag.z + hp.z;
    float t3 = beta * xr.w + (1.f - beta) * ag.w + hp.w;
    float sm = t0 + t1 + t2 + t3;
    float sq = t0 * t0 + t1 * t1 + t2 * t2 + t3 * t3;
#pragma unroll
    for (int o = 16; o; o >>= 1) {
        sm += __shfl_xor_sync(0xffffffffu, sm, o);
        sq += __shfl_xor_sync(0xffffffffu, sq, o);
    }
    float mu = sm * (1.f / 128.f);
    float var = sq * (1.f / 128.f) - mu * mu;
    float rs = rsqrtf(var + 1e-5f);
    float4 o4;
    o4.x = (t0 - mu) * rs * g1[ch]     + b1[ch];
    o4.y = (t1 - mu) * rs * g1[ch + 1] + b1[ch + 1];
    o4.z = (t2 - mu) * rs * g1[ch + 2] + b1[ch + 2];
    o4.w = (t3 - mu) * rs * g1[ch + 3] + b1[ch + 3];
    *(float4*)&g_h[(size_t)n * Dd + ch] = o4;
}

// ---------------- node: h = LN(ff2_out + h) ----------------
__global__ void __launch_bounds__(256) add_ln_k(
    const float* __restrict__ g2, const float* __restrict__ b2)
{
    int warp = threadIdx.x >> 5, lane = threadIdx.x & 31;
    int n = blockIdx.x * 8 + warp;
    if (n >= Nn) return;
    int ch = lane * 4;
    float4 f  = *(const float4*)&g_agg[(size_t)n * Dd + ch];
    float4 hp = *(const float4*)&g_h[(size_t)n * Dd + ch];
    float t0 = f.x + hp.x, t1 = f.y + hp.y, t2 = f.z + hp.z, t3 = f.w + hp.w;
    float sm = t0 + t1 + t2 + t3;
    float sq = t0 * t0 + t1 * t1 + t2 * t2 + t3 * t3;
#pragma unroll
    for (int o = 16; o; o >>= 1) {
        sm += __shfl_xor_sync(0xffffffffu, sm, o);
        sq += __shfl_xor_sync(0xffffffffu, sq, o);
    }
    float mu = sm * (1.f / 128.f);
    float var = sq * (1.f / 128.f) - mu * mu;
    float rs = rsqrtf(var + 1e-5f);
    float4 o4;
    o4.x = (t0 - mu) * rs * g2[ch]     + b2[ch];
    o4.y = (t1 - mu) * rs * g2[ch + 1] + b2[ch + 1];
    o4.z = (t2 - mu) * rs * g2[ch + 2] + b2[ch + 2];
    o4.w = (t3 - mu) * rs * g2[ch + 3] + b2[ch + 3];
    *(float4*)&g_h[(size_t)n * Dd + ch] = o4;
}

// ---------------- pooling ----------------
__global__ void zero_pool_k()
{
    int i = blockIdx.x * blockDim.x + threadIdx.x;
    int st = gridDim.x * blockDim.x;
    for (int j = i; j < Bb * Dd; j += st) g_pool[j] = 0.f;
    for (int j = i; j < Bb; j += st) g_cnt[j] = 0.f;
}

__global__ void __launch_bounds__(256) pool_k(const int* __restrict__ batch)
{
    int warp = threadIdx.x >> 5, lane = threadIdx.x & 31;
    int n = blockIdx.x * 8 + warp;
    if (n >= Nn) return;
    int b = batch[n];
    int ch = lane * 4;
    float4 h4 = *(const float4*)&g_h[(size_t)n * Dd + ch];
    float* dp = &g_pool[(size_t)b * Dd + ch];
    asm volatile("red.global.add.v4.f32 [%0], {%1,%2,%3,%4};"
                 :: "l"(dp), "f"(h4.x), "f"(h4.y), "f"(h4.z), "f"(h4.w) : "memory");
    if (lane == 0) atomicAdd(&g_cnt[b], 1.f);
}

__global__ void __launch_bounds__(256) pool_div_k()
{
    int warp = threadIdx.x >> 5, lane = threadIdx.x & 31;
    int b = blockIdx.x * 8 + warp;
    if (b >= Bb) return;
    float c = fmaxf(g_cnt[b], 1.f);
    int ch = lane * 4;
    float4 p = *(const float4*)&g_pool[(size_t)b * Dd + ch];
    p.x /= c; p.y /= c; p.z /= c; p.w /= c;
    *(float4*)&g_pool[(size_t)b * Dd + ch] = p;
}

// ---------------- host ----------------
extern "C" void kernel_launch(void* const* d_in, const int* in_sizes, int n_in,
                              void* d_out, int out_size)
{
    (void)in_sizes; (void)n_in; (void)out_size;
    const float* x     = (const float*)d_in[0];
    const float* ea    = (const float*)d_in[1];
    const int*   ei    = (const int*)  d_in[2];
    const int*   batch = (const int*)  d_in[3];
    const float* Wemb  = (const float*)d_in[4];
    const float* bemb  = (const float*)d_in[5];
    const float* Wout  = (const float*)d_in[6];
    const float* bout  = (const float*)d_in[7];
    const float* Wq = (const float*)d_in[8];  const float* bq = (const float*)d_in[9];
    const float* Wk = (const float*)d_in[10]; const float* bk = (const float*)d_in[11];
    const float* Wv = (const float*)d_in[12]; const float* bv = (const float*)d_in[13];
    const float* We = (const float*)d_in[14]; const float* be = (const float*)d_in[15];
    const float* Ws = (const float*)d_in[16]; const float* bs = (const float*)d_in[17];
    const float* Wbeta = (const float*)d_in[18];
    const float* g1 = (const float*)d_in[19]; const float* b1 = (const float*)d_in[20];
    const float* g2 = (const float*)d_in[21]; const float* b2 = (const float*)d_in[22];
    const float* Wf1 = (const float*)d_in[23]; const float* bf1 = (const float*)d_in[24];
    const float* Wf2 = (const float*)d_in[25]; const float* bf2 = (const float*)d_in[26];
    float* out = (float*)d_out;

    float *p_h, *p_qkvs, *p_ff, *p_agg, *p_packW, *p_packb, *p_pool;
    cudaGetSymbolAddress((void**)&p_h,     g_h);
    cudaGetSymbolAddress((void**)&p_qkvs,  g_qkvs);
    cudaGetSymbolAddress((void**)&p_ff,    g_ff);
    cudaGetSymbolAddress((void**)&p_agg,   g_agg);
    cudaGetSymbolAddress((void**)&p_packW, g_packW);
    cudaGetSymbolAddress((void**)&p_packb, g_packb);
    cudaGetSymbolAddress((void**)&p_pool,  g_pool);

    dim3 blk(256);
    const int gy = (Nn + 127) / 128;          // 391 row tiles
    const int eg = (Ee + 7) / 8;              // 75000 edge blocks
    const int ng = (Nn + 7) / 8;              // 6250 node blocks

    // h = x @ Wemb + bemb
    gemm_bias_k<false><<<dim3(1, gy), blk>>>(x, Wemb, bemb, p_h, Nn, Dd, FA);

    for (int l = 0; l < Ll; l++) {
        pack_qkvs_k<<<(Dd * 4 * Dd + 255) / 256, blk>>>(Wq, Wk, Wv, Ws, bq, bk, bv, bs, l);
        gemm_bias_k<false><<<dim3(4, gy), blk>>>(p_h, p_packW, p_packb, p_qkvs, Nn, 4 * Dd, Dd);
        zero_layer_k<<<4096, blk>>>();
        edge_pass1_k<<<eg, blk>>>(ei, ea, We + (size_t)l * EDd * Dd, be + l * Dd);
        edge_pass2_k<<<eg, blk>>>(ei, ea, We + (size_t)l * EDd * Dd, be + l * Dd);
        node_gate_ln1_k<<<ng, blk>>>(Wbeta + l * 3 * Dd, g1 + l * Dd, b1 + l * Dd);
        gemm_bias_k<true ><<<dim3(4, gy), blk>>>(p_h, Wf1 + (size_t)l * Dd * DFFd, bf1 + l * DFFd, p_ff, Nn, DFFd, Dd);
        gemm_bias_k<false><<<dim3(1, gy), blk>>>(p_ff, Wf2 + (size_t)l * DFFd * Dd, bf2 + l * Dd, p_agg, Nn, Dd, DFFd);
        add_ln_k<<<ng, blk>>>(g2 + l * Dd, b2 + l * Dd);
    }

    zero_pool_k<<<256, blk>>>();
    pool_k<<<ng, blk>>>(batch);
    pool_div_k<<<(Bb + 7) / 8, blk>>>();
    gemm_bias_k<false><<<dim3(1, (Bb + 127) / 128), blk>>>(p_pool, Wout, bout, out, Bb, Dd, Dd);
}

// round 3
// speedup vs baseline: 1.1181x; 1.1181x over previous
#include <cuda_runtime.h>
#include <cuda_bf16.h>
#include <math.h>
#include <cstdint>

#define Nn   50000
#define Ee   600000
#define FA   78
#define Dd   128
#define Hh   8
#define EDd  12
#define Ll   4
#define Bb   512
#define DFFd 512
#define KS   512          // row stride of pre-split B (bf16) scratch

// ---------------- scratch (device globals; no runtime allocation) ----------------
__device__ float    g_h[(size_t)Nn * Dd];
__device__ float    g_qkvs[(size_t)Nn * 4 * Dd];
__device__ float    g_ff[(size_t)Nn * DFFd];
__device__ float    g_agg[(size_t)Nn * Dd];
__device__ float    g_alpha[(size_t)Ee * Hh];
__device__ unsigned g_mkey[Nn * Hh];
__device__ float    g_den[Nn * Hh];
__device__ float    g_packb[4 * Dd];
__device__ float    g_pool[Bb * Dd];
__device__ float    g_cnt[Bb];
__device__ unsigned short g_Bth[(size_t)512 * KS];   // B^T hi (bf16 bits), [n][k]
__device__ unsigned short g_Btl[(size_t)512 * KS];   // B^T lo (bf16 bits), [n][k]

// monotone float <-> uint key (for atomicMax on float via unsigned)
__device__ __forceinline__ unsigned f2key(float f) {
    unsigned u = __float_as_uint(f);
    return (u & 0x80000000u) ? ~u : (u | 0x80000000u);
}
__device__ __forceinline__ float key2f(unsigned k) {
    unsigned u = (k & 0x80000000u) ? (k ^ 0x80000000u) : ~k;
    return __uint_as_float(u);
}

// ---------------- prep: W[K,N] fp32 -> B^T hi/lo bf16 [N, KS] ----------------
__global__ void prep_b_k(const float* __restrict__ W, int K, int N, int n_off) {
    int Kpad = ((K + 127) >> 7) << 7;
    int i = blockIdx.x * 256 + threadIdx.x;
    if (i >= N * Kpad) return;
    int n = i / Kpad, k = i - n * Kpad;
    float v = (k < K) ? W[(size_t)k * N + n] : 0.f;
    __nv_bfloat16 h = __float2bfloat16(v);
    __nv_bfloat16 lo = __float2bfloat16(v - __bfloat162float(h));
    g_Bth[(size_t)(n_off + n) * KS + k] = __bfloat16_as_ushort(h);
    g_Btl[(size_t)(n_off + n) * KS + k] = __bfloat16_as_ushort(lo);
}

__global__ void pack_bias4_k(const float* __restrict__ bq, const float* __restrict__ bk,
                             const float* __restrict__ bv, const float* __restrict__ bs, int l) {
    int idx = blockIdx.x * 256 + threadIdx.x;
    if (idx < 4 * Dd) {
        int s = idx >> 7, j = idx & 127;
        const float* bb = (s == 0) ? bq : (s == 1) ? bk : (s == 2) ? bv : bs;
        g_packb[idx] = bb[l * Dd + j];
    }
}

// ---------------- HMMA split-bf16 GEMM: C = A[M,K] @ B + bias (B pre-split [N][K]) ----
// CTA tile 128x128, K chunk 128. 8 warps, warp tile 32(m) x 64(n).
// 3-pass split: Ah*Bh + Ah*Bl + Al*Bh accumulated in fp32.
#define LDA_S 136                       // bf16 elems per smem row (128 + 8 pad)
#define SM_TILE (128 * LDA_S * 2)       // 34816 bytes per tile
#define SMEM_GEMM_BYTES (4 * SM_TILE)   // Ah, Al, Bh, Bl

__device__ __forceinline__ void mma_bf16(float& c0, float& c1, float& c2, float& c3,
                                         uint32_t a0, uint32_t a1, uint32_t a2, uint32_t a3,
                                         uint32_t b0, uint32_t b1) {
    asm volatile(
        "mma.sync.aligned.m16n8k16.row.col.f32.bf16.bf16.f32 "
        "{%0,%1,%2,%3}, {%4,%5,%6,%7}, {%8,%9}, {%0,%1,%2,%3};"
        : "+f"(c0), "+f"(c1), "+f"(c2), "+f"(c3)
        : "r"(a0), "r"(a1), "r"(a2), "r"(a3), "r"(b0), "r"(b1));
}

__global__ void __launch_bounds__(256) gemm_tc_k(
    const float* __restrict__ A, int lda, int M, int K,
    const unsigned short* __restrict__ Bth, const unsigned short* __restrict__ Btl,
    const float* __restrict__ bias, float* __restrict__ C, int Nfull, int relu)
{
    extern __shared__ __align__(16) unsigned short smem[];
    unsigned short* sAh = smem;
    unsigned short* sAl = smem + 128 * LDA_S;
    unsigned short* sBh = smem + 2 * 128 * LDA_S;
    unsigned short* sBl = smem + 3 * 128 * LDA_S;

    const int tid  = threadIdx.x;
    const int warp = tid >> 5, lane = tid & 31;
    const int wm = warp & 3;          // 4 m-blocks of 32
    const int wn = warp >> 2;         // 2 n-blocks of 64
    const int bm = blockIdx.x << 7;
    const int bn = blockIdx.y << 7;
    const int k_chunks = (K + 127) >> 7;

    float acc[2][8][4];
#pragma unroll
    for (int i = 0; i < 2; i++)
#pragma unroll
        for (int j = 0; j < 8; j++)
#pragma unroll
            for (int q = 0; q < 4; q++) acc[i][j][q] = 0.f;

    const int lr  = tid >> 1;             // 0..127: row handled by this thread
    const int lc0 = (tid & 1) * 64;       // column half

    for (int kc = 0; kc < k_chunks; kc++) {
        const int k0 = kc << 7;
        // ---- A tile: fp32 gmem -> bf16 hi/lo smem ----
        {
            const int rg = bm + lr;
            const bool rok = rg < M;
            const float* ap = A + (size_t)rg * lda + k0 + lc0;
#pragma unroll
            for (int i = 0; i < 64; i += 2) {
                int k = k0 + lc0 + i;
                float2 v = make_float2(0.f, 0.f);
                if (rok) {
                    if (k + 1 < K) v = *(const float2*)(ap + i);
                    else if (k < K) v.x = ap[i];
                }
                __nv_bfloat16 h0 = __float2bfloat16(v.x);
                __nv_bfloat16 h1 = __float2bfloat16(v.y);
                __nv_bfloat16 l0 = __float2bfloat16(v.x - __bfloat162float(h0));
                __nv_bfloat16 l1 = __float2bfloat16(v.y - __bfloat162float(h1));
                uint32_t hp = (uint32_t)__bfloat16_as_ushort(h0) | ((uint32_t)__bfloat16_as_ushort(h1) << 16);
                uint32_t lp = (uint32_t)__bfloat16_as_ushort(l0) | ((uint32_t)__bfloat16_as_ushort(l1) << 16);
                *(uint32_t*)&sAh[lr * LDA_S + lc0 + i] = hp;
                *(uint32_t*)&sAl[lr * LDA_S + lc0 + i] = lp;
            }
        }
        // ---- B tile: pre-split bf16 gmem [n][KS] -> smem [n][LDA_S] ----
        {
            const unsigned short* gbh = Bth + (size_t)(bn + lr) * KS + k0 + lc0;
            const unsigned short* gbl = Btl + (size_t)(bn + lr) * KS + k0 + lc0;
#pragma unroll
            for (int i = 0; i < 8; i++) {
                uint4 vh = *(const uint4*)(gbh + i * 8);
                uint4 vl = *(const uint4*)(gbl + i * 8);
                *(uint4*)&sBh[lr * LDA_S + lc0 + i * 8] = vh;
                *(uint4*)&sBl[lr * LDA_S + lc0 + i * 8] = vl;
            }
        }
        __syncthreads();

        // ---- MMA main loop over 8 k-steps of 16 ----
        const int qr = lane >> 2;          // 0..7
        const int qc = (lane & 3) * 2;     // 0,2,4,6
#pragma unroll
        for (int ks = 0; ks < 8; ks++) {
            const int kk = ks * 16;
            uint32_t ah[2][4], al[2][4];
#pragma unroll
            for (int mb = 0; mb < 2; mb++) {
                int r0 = wm * 32 + mb * 16 + qr;
                int c  = kk + qc;
                ah[mb][0] = *(const uint32_t*)&sAh[r0 * LDA_S + c];
                ah[mb][1] = *(const uint32_t*)&sAh[(r0 + 8) * LDA_S + c];
                ah[mb][2] = *(const uint32_t*)&sAh[r0 * LDA_S + c + 8];
                ah[mb][3] = *(const uint32_t*)&sAh[(r0 + 8) * LDA_S + c + 8];
                al[mb][0] = *(const uint32_t*)&sAl[r0 * LDA_S + c];
                al[mb][1] = *(const uint32_t*)&sAl[(r0 + 8) * LDA_S + c];
                al[mb][2] = *(const uint32_t*)&sAl[r0 * LDA_S + c + 8];
                al[mb][3] = *(const uint32_t*)&sAl[(r0 + 8) * LDA_S + c + 8];
            }
            uint32_t bh[8][2], bl[8][2];
#pragma unroll
            for (int nb = 0; nb < 8; nb++) {
                int n0 = wn * 64 + nb * 8 + qr;
                int c  = kk + qc;
                bh[nb][0] = *(const uint32_t*)&sBh[n0 * LDA_S + c];
                bh[nb][1] = *(const uint32_t*)&sBh[n0 * LDA_S + c + 8];
                bl[nb][0] = *(const uint32_t*)&sBl[n0 * LDA_S + c];
                bl[nb][1] = *(const uint32_t*)&sBl[n0 * LDA_S + c + 8];
            }
#pragma unroll
            for (int mb = 0; mb < 2; mb++)
#pragma unroll
                for (int nb = 0; nb < 8; nb++) {
                    mma_bf16(acc[mb][nb][0], acc[mb][nb][1], acc[mb][nb][2], acc[mb][nb][3],
                             ah[mb][0], ah[mb][1], ah[mb][2], ah[mb][3], bh[nb][0], bh[nb][1]);
                    mma_bf16(acc[mb][nb][0], acc[mb][nb][1], acc[mb][nb][2], acc[mb][nb][3],
                             ah[mb][0], ah[mb][1], ah[mb][2], ah[mb][3], bl[nb][0], bl[nb][1]);
                    mma_bf16(acc[mb][nb][0], acc[mb][nb][1], acc[mb][nb][2], acc[mb][nb][3],
                             al[mb][0], al[mb][1], al[mb][2], al[mb][3], bh[nb][0], bh[nb][1]);
                }
        }
        __syncthreads();
    }

    // ---- epilogue ----
    const int qr = lane >> 2;
    const int qc = (lane & 3) * 2;
#pragma unroll
    for (int mb = 0; mb < 2; mb++) {
        int r0 = bm + wm * 32 + mb * 16 + qr;
#pragma unroll
        for (int half = 0; half < 2; half++) {
            int r = r0 + half * 8;
            if (r >= M) continue;
            float* cp = C + (size_t)r * Nfull + bn + wn * 64;
#pragma unroll
            for (int nb = 0; nb < 8; nb++) {
                int cn = nb * 8 + qc;
                float v0 = acc[mb][nb][half * 2 + 0] + bias[bn + wn * 64 + cn];
                float v1 = acc[mb][nb][half * 2 + 1] + bias[bn + wn * 64 + cn + 1];
                if (relu) { v0 = fmaxf(v0, 0.f); v1 = fmaxf(v1, 0.f); }
                *(float2*)(cp + cn) = make_float2(v0, v1);
            }
        }
    }
}

// ---------------- zero per-layer edge state ----------------
__global__ void zero_layer_k() {
    int i = blockIdx.x * blockDim.x + threadIdx.x;
    int st = gridDim.x * blockDim.x;
    for (int j = i; j < Nn * Hh; j += st) { g_mkey[j] = 0u; g_den[j] = 0.f; }
    for (int j = i; j < Nn * Dd; j += st) g_agg[j] = 0.f;
}

// ---------------- edge pass 1: alpha + segment max ----------------
__global__ void __launch_bounds__(256) edge_pass1_k(
    const int* __restrict__ ei, const float* __restrict__ ea,
    const float* __restrict__ We, const float* __restrict__ be)
{
    __shared__ float sWe[EDd * Dd];
    __shared__ float sbe[Dd];
    for (int i = threadIdx.x; i < EDd * Dd; i += 256) sWe[i] = We[i];
    for (int i = threadIdx.x; i < Dd; i += 256) sbe[i] = be[i];
    __syncthreads();
    int warp = threadIdx.x >> 5, lane = threadIdx.x & 31;
    int eid = blockIdx.x * 8 + warp;
    if (eid >= Ee) return;
    int src = ei[eid], dst = ei[Ee + eid];
    float eav = (lane < EDd) ? ea[(size_t)eid * EDd + lane] : 0.f;
    int ch = lane * 4;
    float e0 = sbe[ch], e1 = sbe[ch + 1], e2 = sbe[ch + 2], e3 = sbe[ch + 3];
#pragma unroll
    for (int t = 0; t < EDd; t++) {
        float a = __shfl_sync(0xffffffffu, eav, t);
        e0 += a * sWe[t * Dd + ch + 0];
        e1 += a * sWe[t * Dd + ch + 1];
        e2 += a * sWe[t * Dd + ch + 2];
        e3 += a * sWe[t * Dd + ch + 3];
    }
    float4 qd = *(const float4*)&g_qkvs[(size_t)dst * 512 + ch];
    float4 ks = *(const float4*)&g_qkvs[(size_t)src * 512 + 128 + ch];
    float p = qd.x * (ks.x + e0) + qd.y * (ks.y + e1) +
              qd.z * (ks.z + e2) + qd.w * (ks.w + e3);
    p += __shfl_xor_sync(0xffffffffu, p, 1);
    p += __shfl_xor_sync(0xffffffffu, p, 2);
    if ((lane & 3) == 0) {
        float alpha = p * 0.25f;
        int h = lane >> 2;
        g_alpha[(size_t)eid * Hh + h] = alpha;
        atomicMax(&g_mkey[dst * Hh + h], f2key(alpha));
    }
}

// ---------------- edge pass 2: exp, denominator, message accumulation -------------
__global__ void __launch_bounds__(256) edge_pass2_k(
    const int* __restrict__ ei, const float* __restrict__ ea,
    const float* __restrict__ We, const float* __restrict__ be)
{
    __shared__ float sWe[EDd * Dd];
    __shared__ float sbe[Dd];
    for (int i = threadIdx.x; i < EDd * Dd; i += 256) sWe[i] = We[i];
    for (int i = threadIdx.x; i < Dd; i += 256) sbe[i] = be[i];
    __syncthreads();
    int warp = threadIdx.x >> 5, lane = threadIdx.x & 31;
    int eid = blockIdx.x * 8 + warp;
    if (eid >= Ee) return;
    int src = ei[eid], dst = ei[Ee + eid];
    float eav = (lane < EDd) ? ea[(size_t)eid * EDd + lane] : 0.f;
    int ch = lane * 4;
    float e0 = sbe[ch], e1 = sbe[ch + 1], e2 = sbe[ch + 2], e3 = sbe[ch + 3];
#pragma unroll
    for (int t = 0; t < EDd; t++) {
        float a = __shfl_sync(0xffffffffu, eav, t);
        e0 += a * sWe[t * Dd + ch + 0];
        e1 += a * sWe[t * Dd + ch + 1];
        e2 += a * sWe[t * Dd + ch + 2];
        e3 += a * sWe[t * Dd + ch + 3];
    }
    int h = lane >> 2;
    float m = key2f(g_mkey[dst * Hh + h]);
    float alpha = g_alpha[(size_t)eid * Hh + h];
    float ex = expf(alpha - m);
    if ((lane & 3) == 0) atomicAdd(&g_den[dst * Hh + h], ex);
    float4 vs = *(const float4*)&g_qkvs[(size_t)src * 512 + 256 + ch];
    float m0 = (vs.x + e0) * ex, m1 = (vs.y + e1) * ex;
    float m2 = (vs.z + e2) * ex, m3 = (vs.w + e3) * ex;
    float* dp = &g_agg[(size_t)dst * Dd + ch];
    asm volatile("red.global.add.v4.f32 [%0], {%1,%2,%3,%4};"
                 :: "l"(dp), "f"(m0), "f"(m1), "f"(m2), "f"(m3) : "memory");
}

// ---------------- node: normalize agg, beta gate, residual, LN1 ----------------
__global__ void __launch_bounds__(256) node_gate_ln1_k(
    const float* __restrict__ wb, const float* __restrict__ g1,
    const float* __restrict__ b1)
{
    int warp = threadIdx.x >> 5, lane = threadIdx.x & 31;
    int n = blockIdx.x * 8 + warp;
    if (n >= Nn) return;
    int ch = lane * 4;
    float4 ag = *(const float4*)&g_agg[(size_t)n * Dd + ch];
    float den = g_den[n * Hh + (lane >> 2)] + 1e-16f;
    float inv = 1.f / den;
    ag.x *= inv; ag.y *= inv; ag.z *= inv; ag.w *= inv;
    float4 xr = *(const float4*)&g_qkvs[(size_t)n * 512 + 384 + ch];
    float s =
        ag.x * wb[ch] + ag.y * wb[ch + 1] + ag.z * wb[ch + 2] + ag.w * wb[ch + 3] +
        xr.x * wb[128 + ch] + xr.y * wb[128 + ch + 1] + xr.z * wb[128 + ch + 2] + xr.w * wb[128 + ch + 3] +
        (ag.x - xr.x) * wb[256 + ch] + (ag.y - xr.y) * wb[256 + ch + 1] +
        (ag.z - xr.z) * wb[256 + ch + 2] + (ag.w - xr.w) * wb[256 + ch + 3];
#pragma unroll
    for (int o = 16; o; o >>= 1) s += __shfl_xor_sync(0xffffffffu, s, o);
    float beta = 1.f / (1.f + expf(-s));
    float4 hp = *(const float4*)&g_h[(size_t)n * Dd + ch];
    float t0 = beta * xr.x + (1.f - beta) * ag.x + hp.x;
    float t1 = beta * xr.y + (1.f - beta) * ag.y + hp.y;
    float t2 = beta * xr.z + (1.f - beta) * ag.z + hp.z;
    float t3 = beta * xr.w + (1.f - beta) * ag.w + hp.w;
    float sm = t0 + t1 + t2 + t3;
    float sq = t0 * t0 + t1 * t1 + t2 * t2 + t3 * t3;
#pragma unroll
    for (int o = 16; o; o >>= 1) {
        sm += __shfl_xor_sync(0xffffffffu, sm, o);
        sq += __shfl_xor_sync(0xffffffffu, sq, o);
    }
    float mu = sm * (1.f / 128.f);
    float var = sq * (1.f / 128.f) - mu * mu;
    float rs = rsqrtf(var + 1e-5f);
    float4 o4;
    o4.x = (t0 - mu) * rs * g1[ch]     + b1[ch];
    o4.y = (t1 - mu) * rs * g1[ch + 1] + b1[ch + 1];
    o4.z = (t2 - mu) * rs * g1[ch + 2] + b1[ch + 2];
    o4.w = (t3 - mu) * rs * g1[ch + 3] + b1[ch + 3];
    *(float4*)&g_h[(size_t)n * Dd + ch] = o4;
}

// ---------------- node: h = LN(ff2_out + h) ----------------
__global__ void __launch_bounds__(256) add_ln_k(
    const float* __restrict__ g2, const float* __restrict__ b2)
{
    int warp = threadIdx.x >> 5, lane = threadIdx.x & 31;
    int n = blockIdx.x * 8 + warp;
    if (n >= Nn) return;
    int ch = lane * 4;
    float4 f  = *(const float4*)&g_agg[(size_t)n * Dd + ch];
    float4 hp = *(const float4*)&g_h[(size_t)n * Dd + ch];
    float t0 = f.x + hp.x, t1 = f.y + hp.y, t2 = f.z + hp.z, t3 = f.w + hp.w;
    float sm = t0 + t1 + t2 + t3;
    float sq = t0 * t0 + t1 * t1 + t2 * t2 + t3 * t3;
#pragma unroll
    for (int o = 16; o; o >>= 1) {
        sm += __shfl_xor_sync(0xffffffffu, sm, o);
        sq += __shfl_xor_sync(0xffffffffu, sq, o);
    }
    float mu = sm * (1.f / 128.f);
    float var = sq * (1.f / 128.f) - mu * mu;
    float rs = rsqrtf(var + 1e-5f);
    float4 o4;
    o4.x = (t0 - mu) * rs * g2[ch]     + b2[ch];
    o4.y = (t1 - mu) * rs * g2[ch + 1] + b2[ch + 1];
    o4.z = (t2 - mu) * rs * g2[ch + 2] + b2[ch + 2];
    o4.w = (t3 - mu) * rs * g2[ch + 3] + b2[ch + 3];
    *(float4*)&g_h[(size_t)n * Dd + ch] = o4;
}

// ---------------- pooling ----------------
__global__ void zero_pool_k() {
    int i = blockIdx.x * blockDim.x + threadIdx.x;
    int st = gridDim.x * blockDim.x;
    for (int j = i; j < Bb * Dd; j += st) g_pool[j] = 0.f;
    for (int j = i; j < Bb; j += st) g_cnt[j] = 0.f;
}

__global__ void __launch_bounds__(256) pool_k(const int* __restrict__ batch) {
    int warp = threadIdx.x >> 5, lane = threadIdx.x & 31;
    int n = blockIdx.x * 8 + warp;
    if (n >= Nn) return;
    int b = batch[n];
    int ch = lane * 4;
    float4 h4 = *(const float4*)&g_h[(size_t)n * Dd + ch];
    float* dp = &g_pool[(size_t)b * Dd + ch];
    asm volatile("red.global.add.v4.f32 [%0], {%1,%2,%3,%4};"
                 :: "l"(dp), "f"(h4.x), "f"(h4.y), "f"(h4.z), "f"(h4.w) : "memory");
    if (lane == 0) atomicAdd(&g_cnt[b], 1.f);
}

__global__ void __launch_bounds__(256) pool_div_k() {
    int warp = threadIdx.x >> 5, lane = threadIdx.x & 31;
    int b = blockIdx.x * 8 + warp;
    if (b >= Bb) return;
    float c = fmaxf(g_cnt[b], 1.f);
    int ch = lane * 4;
    float4 p = *(const float4*)&g_pool[(size_t)b * Dd + ch];
    p.x /= c; p.y /= c; p.z /= c; p.w /= c;
    *(float4*)&g_pool[(size_t)b * Dd + ch] = p;
}

// ---------------- host ----------------
extern "C" void kernel_launch(void* const* d_in, const int* in_sizes, int n_in,
                              void* d_out, int out_size)
{
    (void)in_sizes; (void)n_in; (void)out_size;
    const float* x     = (const float*)d_in[0];
    const float* ea    = (const float*)d_in[1];
    const int*   ei    = (const int*)  d_in[2];
    const int*   batch = (const int*)  d_in[3];
    const float* Wemb  = (const float*)d_in[4];
    const float* bemb  = (const float*)d_in[5];
    const float* Wout  = (const float*)d_in[6];
    const float* bout  = (const float*)d_in[7];
    const float* Wq = (const float*)d_in[8];  const float* bq = (const float*)d_in[9];
    const float* Wk = (const float*)d_in[10]; const float* bk = (const float*)d_in[11];
    const float* Wv = (const float*)d_in[12]; const float* bv = (const float*)d_in[13];
    const float* We = (const float*)d_in[14]; const float* be = (const float*)d_in[15];
    const float* Ws = (const float*)d_in[16]; const float* bs = (const float*)d_in[17];
    const float* Wbeta = (const float*)d_in[18];
    const float* g1 = (const float*)d_in[19]; const float* b1 = (const float*)d_in[20];
    const float* g2 = (const float*)d_in[21]; const float* b2 = (const float*)d_in[22];
    const float* Wf1 = (const float*)d_in[23]; const float* bf1 = (const float*)d_in[24];
    const float* Wf2 = (const float*)d_in[25]; const float* bf2 = (const float*)d_in[26];
    float* out = (float*)d_out;

    float *p_h, *p_qkvs, *p_ff, *p_agg, *p_packb, *p_pool;
    unsigned short *p_Bth, *p_Btl;
    cudaGetSymbolAddress((void**)&p_h,     g_h);
    cudaGetSymbolAddress((void**)&p_qkvs,  g_qkvs);
    cudaGetSymbolAddress((void**)&p_ff,    g_ff);
    cudaGetSymbolAddress((void**)&p_agg,   g_agg);
    cudaGetSymbolAddress((void**)&p_packb, g_packb);
    cudaGetSymbolAddress((void**)&p_pool,  g_pool);
    cudaGetSymbolAddress((void**)&p_Bth,   g_Bth);
    cudaGetSymbolAddress((void**)&p_Btl,   g_Btl);

    cudaFuncSetAttribute(gemm_tc_k, cudaFuncAttributeMaxDynamicSharedMemorySize, SMEM_GEMM_BYTES);

    dim3 blk(256);
    const int mt = (Nn + 127) / 128;          // 391 row tiles
    const int eg = (Ee + 7) / 8;
    const int ng = (Nn + 7) / 8;

    // embed: h = x @ Wemb + bemb
    prep_b_k<<<(Dd * Dd + 255) / 256, blk>>>(Wemb, FA, Dd, 0);
    gemm_tc_k<<<dim3(mt, 1), blk, SMEM_GEMM_BYTES>>>(x, FA, Nn, FA, p_Bth, p_Btl, bemb, p_h, Dd, 0);

    for (int l = 0; l < Ll; l++) {
        // QKV+skip packed B^T rows: 0-127 Wq, 128-255 Wk, 256-383 Wv, 384-511 Wskip
        prep_b_k<<<64, blk>>>(Wq + (size_t)l * Dd * Dd, Dd, Dd, 0);
        prep_b_k<<<64, blk>>>(Wk + (size_t)l * Dd * Dd, Dd, Dd, 128);
        prep_b_k<<<64, blk>>>(Wv + (size_t)l * Dd * Dd, Dd, Dd, 256);
        prep_b_k<<<64, blk>>>(Ws + (size_t)l * Dd * Dd, Dd, Dd, 384);
        pack_bias4_k<<<2, blk>>>(bq, bk, bv, bs, l);
        gemm_tc_k<<<dim3(mt, 4), blk, SMEM_GEMM_BYTES>>>(p_h, Dd, Nn, Dd, p_Bth, p_Btl, p_packb, p_qkvs, 4 * Dd, 0);

        zero_layer_k<<<4096, blk>>>();
        edge_pass1_k<<<eg, blk>>>(ei, ea, We + (size_t)l * EDd * Dd, be + l * Dd);
        edge_pass2_k<<<eg, blk>>>(ei, ea, We + (size_t)l * EDd * Dd, be + l * Dd);
        node_gate_ln1_k<<<ng, blk>>>(Wbeta + l * 3 * Dd, g1 + l * Dd, b1 + l * Dd);

        prep_b_k<<<256, blk>>>(Wf1 + (size_t)l * Dd * DFFd, Dd, DFFd, 0);
        gemm_tc_k<<<dim3(mt, 4), blk, SMEM_GEMM_BYTES>>>(p_h, Dd, Nn, Dd, p_Bth, p_Btl, bf1 + l * DFFd, p_ff, DFFd, 1);

        prep_b_k<<<256, blk>>>(Wf2 + (size_t)l * DFFd * Dd, DFFd, Dd, 0);
        gemm_tc_k<<<dim3(mt, 1), blk, SMEM_GEMM_BYTES>>>(p_ff, DFFd, Nn, DFFd, p_Bth, p_Btl, bf2 + l * Dd, p_agg, Dd, 0);

        add_ln_k<<<ng, blk>>>(g2 + l * Dd, b2 + l * Dd);
    }

    zero_pool_k<<<256, blk>>>();
    pool_k<<<ng, blk>>>(batch);
    pool_div_k<<<(Bb + 7) / 8, blk>>>();
    prep_b_k<<<64, blk>>>(Wout, Dd, Dd, 0);
    gemm_tc_k<<<dim3(4, 1), blk, SMEM_GEMM_BYTES>>>(p_pool, Dd, Bb, Dd, p_Bth, p_Btl, bout, out, Dd, 0);
}

// round 4
// speedup vs baseline: 1.8816x; 1.6828x over previous
#include <cuda_runtime.h>
#include <cuda_bf16.h>
#include <math.h>
#include <cstdint>

#define Nn   50000
#define Ee   600000
#define FA   78
#define Dd   128
#define Hh   8
#define EDd  12
#define Ll   4
#define Bb   512
#define DFFd 512
#define KS   512            // row stride (shorts) of pre-split B
#define MP   50048          // padded rows for A buffers

typedef unsigned short ushort_t;

// ---------------- scratch (device globals; no runtime allocation) ----------------
__device__ float    g_h[(size_t)Nn * Dd];
__device__ float    g_qkvs[(size_t)Nn * 4 * Dd];
__device__ float    g_agg[(size_t)Nn * Dd];
__device__ float    g_den[Nn * Hh];
__device__ float    g_packb[4 * Dd];
__device__ float    g_pool[Bb * Dd];
__device__ float    g_cnt[Bb];
__device__ ushort_t g_Bth[(size_t)512 * KS];          // B^T hi bf16 [n][k]
__device__ ushort_t g_Btl[(size_t)512 * KS];          // B^T lo bf16 [n][k]
__device__ ushort_t g_Ath[(size_t)MP * Dd];           // A hi (h / x / pool), stride 128
__device__ ushort_t g_Atl[(size_t)MP * Dd];
__device__ ushort_t g_Fth[(size_t)MP * DFFd];         // ff hi, stride 512
__device__ ushort_t g_Ftl[(size_t)MP * DFFd];

// ---------------- helpers ----------------
__device__ __forceinline__ uint32_t smem_u32(const void* p) {
    uint32_t a;
    asm("{ .reg .u64 t; cvta.to.shared.u64 t, %1; cvt.u32.u64 %0, t; }" : "=r"(a) : "l"(p));
    return a;
}
__device__ __forceinline__ void cp16(uint32_t dst, const void* src) {
    asm volatile("cp.async.ca.shared.global [%0], [%1], 16;" :: "r"(dst), "l"(src));
}
__device__ __forceinline__ void cp_commit() { asm volatile("cp.async.commit_group;" ::: "memory"); }
template <int N> __device__ __forceinline__ void cp_wait() {
    asm volatile("cp.async.wait_group %0;" :: "n"(N) : "memory");
}
__device__ __forceinline__ void ldsm4(uint32_t& r0, uint32_t& r1, uint32_t& r2, uint32_t& r3, uint32_t addr) {
    asm volatile("ldmatrix.sync.aligned.m8n8.x4.shared.b16 {%0,%1,%2,%3}, [%4];"
                 : "=r"(r0), "=r"(r1), "=r"(r2), "=r"(r3) : "r"(addr));
}
__device__ __forceinline__ void mma_bf16(float& c0, float& c1, float& c2, float& c3,
                                         uint32_t a0, uint32_t a1, uint32_t a2, uint32_t a3,
                                         uint32_t b0, uint32_t b1) {
    asm volatile(
        "mma.sync.aligned.m16n8k16.row.col.f32.bf16.bf16.f32 "
        "{%0,%1,%2,%3}, {%4,%5,%6,%7}, {%8,%9}, {%0,%1,%2,%3};"
        : "+f"(c0), "+f"(c1), "+f"(c2), "+f"(c3)
        : "r"(a0), "r"(a1), "r"(a2), "r"(a3), "r"(b0), "r"(b1));
}
__device__ __forceinline__ void split2(float x, float y, uint32_t& hp, uint32_t& lp) {
    __nv_bfloat16 hx = __float2bfloat16(x), hy = __float2bfloat16(y);
    __nv_bfloat16 lx = __float2bfloat16(x - __bfloat162float(hx));
    __nv_bfloat16 ly = __float2bfloat16(y - __bfloat162float(hy));
    hp = (uint32_t)__bfloat16_as_ushort(hx) | ((uint32_t)__bfloat16_as_ushort(hy) << 16);
    lp = (uint32_t)__bfloat16_as_ushort(lx) | ((uint32_t)__bfloat16_as_ushort(ly) << 16);
}

// ---------------- prep: W[K,N] fp32 -> B^T hi/lo bf16 [N, KS] ----------------
__global__ void prep_b_k(const float* __restrict__ W, int K, int N, int n_off) {
    int Kpad = ((K + 127) >> 7) << 7;
    int i = blockIdx.x * 256 + threadIdx.x;
    if (i >= N * Kpad) return;
    int n = i / Kpad, k = i - n * Kpad;
    float v = (k < K) ? W[(size_t)k * N + n] : 0.f;
    __nv_bfloat16 h = __float2bfloat16(v);
    __nv_bfloat16 lo = __float2bfloat16(v - __bfloat162float(h));
    g_Bth[(size_t)(n_off + n) * KS + k] = __bfloat16_as_ushort(h);
    g_Btl[(size_t)(n_off + n) * KS + k] = __bfloat16_as_ushort(lo);
}

// split fp32 matrix -> Ath/Atl (stride 128), zero-pad cols >= ksrc
__global__ void split_a_k(const float* __restrict__ src, int ksrc, int M) {
    int i = blockIdx.x * 256 + threadIdx.x;
    if (i >= M * Dd) return;
    int r = i >> 7, k = i & 127;
    float v = (k < ksrc) ? src[(size_t)r * ksrc + k] : 0.f;
    __nv_bfloat16 h = __float2bfloat16(v);
    __nv_bfloat16 lo = __float2bfloat16(v - __bfloat162float(h));
    g_Ath[(size_t)r * Dd + k] = __bfloat16_as_ushort(h);
    g_Atl[(size_t)r * Dd + k] = __bfloat16_as_ushort(lo);
}

__global__ void pack_bias4_k(const float* __restrict__ bq, const float* __restrict__ bk,
                             const float* __restrict__ bv, const float* __restrict__ bs, int l) {
    int idx = blockIdx.x * 256 + threadIdx.x;
    if (idx < 4 * Dd) {
        int s = idx >> 7, j = idx & 127;
        const float* bb = (s == 0) ? bq : (s == 1) ? bk : (s == 2) ? bv : bs;
        g_packb[idx] = bb[l * Dd + j];
    }
}

// ---------------- pipelined split-bf16 HMMA GEMM ----------------
// A pre-split bf16 hi/lo [Mpad][ksa]; B pre-split [512][KS]. C = A@B^T + bias.
// CTA 128x128, k-chunks of 64, 2-stage cp.async, ldmatrix fragments, 3-pass split.
// OUT: 0 = fp32 C, 1 = split bf16 (Ch/Cl), 2 = both fp32 and split(A buffers).
#define T_STRIDE 72                      // shorts per smem row (64 + 8 pad)
#define TILE_B   (128 * T_STRIDE * 2)    // 18432 bytes
#define STAGE_B  (4 * TILE_B)            // 73728
#define SMEM_G2  (2 * STAGE_B)           // 147456

template <int OUT>
__global__ void __launch_bounds__(256) gemm2_k(
    const ushort_t* __restrict__ Ah, const ushort_t* __restrict__ Al, int ksa,
    int M, int nc,
    const ushort_t* __restrict__ Bh, const ushort_t* __restrict__ Bl,
    const float* __restrict__ bias,
    float* __restrict__ C, ushort_t* __restrict__ Ch, ushort_t* __restrict__ Cl,
    int Nfull, int relu)
{
    extern __shared__ __align__(16) char smem[];
    const uint32_t sb = smem_u32(smem);

    const int tid  = threadIdx.x;
    const int warp = tid >> 5, lane = tid & 31;
    const int wm = warp & 3, wn = warp >> 2;
    const int bm = blockIdx.x << 7;
    const int bn = blockIdx.y << 7;

    const int lrow = tid >> 1;            // 0..127
    const int half = tid & 1;             // column half (64B each)

    float acc[2][8][4];
#pragma unroll
    for (int i = 0; i < 2; i++)
#pragma unroll
        for (int j = 0; j < 8; j++)
#pragma unroll
            for (int q = 0; q < 4; q++) acc[i][j][q] = 0.f;

    // ---- async load of one k-chunk into stage s ----
    auto issue = [&](int c) {
        const int k0 = c << 6;
        const uint32_t st = sb + (c & 1) * STAGE_B;
        const uint32_t drow = lrow * (T_STRIDE * 2) + half * 64;
        const ushort_t* ga  = Ah + (size_t)(bm + lrow) * ksa + k0 + half * 32;
        const ushort_t* gal = Al + (size_t)(bm + lrow) * ksa + k0 + half * 32;
        const ushort_t* gb  = Bh + (size_t)(bn + lrow) * KS  + k0 + half * 32;
        const ushort_t* gbl = Bl + (size_t)(bn + lrow) * KS  + k0 + half * 32;
#pragma unroll
        for (int j = 0; j < 4; j++) {
            cp16(st + drow + j * 16,              ga  + j * 8);
            cp16(st + TILE_B + drow + j * 16,     gal + j * 8);
            cp16(st + 2 * TILE_B + drow + j * 16, gb  + j * 8);
            cp16(st + 3 * TILE_B + drow + j * 16, gbl + j * 8);
        }
        cp_commit();
    };

    issue(0);
    if (nc > 1) issue(1);

    for (int c = 0; c < nc; c++) {
        if (c + 1 < nc) cp_wait<1>(); else cp_wait<0>();
        __syncthreads();
        const uint32_t st = sb + (c & 1) * STAGE_B;
        const uint32_t sAh = st, sAl = st + TILE_B, sBh = st + 2 * TILE_B, sBl = st + 3 * TILE_B;

        // lane-dependent ldmatrix address components
        const int a_r = ((lane >> 3) & 1) * 8 + (lane & 7);
        const int a_c = (lane >> 4) * 8;
        const int b_r = (lane >> 4) * 8 + (lane & 7);
        const int b_c = ((lane >> 3) & 1) * 8;

#pragma unroll
        for (int ksx = 0; ksx < 4; ksx++) {
            const int kk = ksx * 16;
            uint32_t ah[2][4], al[2][4];
#pragma unroll
            for (int mb = 0; mb < 2; mb++) {
                uint32_t off = (uint32_t)((wm * 32 + mb * 16 + a_r) * T_STRIDE + kk + a_c) * 2;
                ldsm4(ah[mb][0], ah[mb][1], ah[mb][2], ah[mb][3], sAh + off);
                ldsm4(al[mb][0], al[mb][1], al[mb][2], al[mb][3], sAl + off);
            }
            uint32_t bh[8][2], bl[8][2];
#pragma unroll
            for (int nbp = 0; nbp < 4; nbp++) {
                uint32_t off = (uint32_t)((wn * 64 + nbp * 16 + b_r) * T_STRIDE + kk + b_c) * 2;
                ldsm4(bh[2 * nbp][0], bh[2 * nbp][1], bh[2 * nbp + 1][0], bh[2 * nbp + 1][1], sBh + off);
                ldsm4(bl[2 * nbp][0], bl[2 * nbp][1], bl[2 * nbp + 1][0], bl[2 * nbp + 1][1], sBl + off);
            }
#pragma unroll
            for (int mb = 0; mb < 2; mb++)
#pragma unroll
                for (int nb = 0; nb < 8; nb++) {
                    mma_bf16(acc[mb][nb][0], acc[mb][nb][1], acc[mb][nb][2], acc[mb][nb][3],
                             ah[mb][0], ah[mb][1], ah[mb][2], ah[mb][3], bh[nb][0], bh[nb][1]);
                    mma_bf16(acc[mb][nb][0], acc[mb][nb][1], acc[mb][nb][2], acc[mb][nb][3],
                             ah[mb][0], ah[mb][1], ah[mb][2], ah[mb][3], bl[nb][0], bl[nb][1]);
                    mma_bf16(acc[mb][nb][0], acc[mb][nb][1], acc[mb][nb][2], acc[mb][nb][3],
                             al[mb][0], al[mb][1], al[mb][2], al[mb][3], bh[nb][0], bh[nb][1]);
                }
        }
        __syncthreads();
        if (c + 2 < nc) issue(c + 2);
    }

    // ---- epilogue ----
    const int qr = lane >> 2;
    const int qc = (lane & 3) * 2;
#pragma unroll
    for (int mb = 0; mb < 2; mb++) {
        int r0 = bm + wm * 32 + mb * 16 + qr;
#pragma unroll
        for (int hf = 0; hf < 2; hf++) {
            int r = r0 + hf * 8;
            if (r >= M) continue;
#pragma unroll
            for (int nb = 0; nb < 8; nb++) {
                int cn = bn + wn * 64 + nb * 8 + qc;
                float v0 = acc[mb][nb][hf * 2 + 0] + bias[cn];
                float v1 = acc[mb][nb][hf * 2 + 1] + bias[cn + 1];
                if (relu) { v0 = fmaxf(v0, 0.f); v1 = fmaxf(v1, 0.f); }
                if (OUT == 0 || OUT == 2)
                    *(float2*)&C[(size_t)r * Nfull + cn] = make_float2(v0, v1);
                if (OUT == 1) {
                    uint32_t hp, lp; split2(v0, v1, hp, lp);
                    *(uint32_t*)&Ch[(size_t)r * Nfull + cn] = hp;
                    *(uint32_t*)&Cl[(size_t)r * Nfull + cn] = lp;
                }
                if (OUT == 2) {
                    uint32_t hp, lp; split2(v0, v1, hp, lp);
                    *(uint32_t*)&g_Ath[(size_t)r * Dd + cn] = hp;
                    *(uint32_t*)&g_Atl[(size_t)r * Dd + cn] = lp;
                }
            }
        }
    }
}

// ---------------- zero per-layer state ----------------
__global__ void zero_layer_k() {
    int i = blockIdx.x * blockDim.x + threadIdx.x;
    int st = gridDim.x * blockDim.x;
    for (int j = i; j < Nn * Hh; j += st) g_den[j] = 0.f;
    for (int j = i; j < Nn * Dd; j += st) g_agg[j] = 0.f;
}

// ---------------- fused edge pass: e-proj, alpha, exp, den + msg atomics ----------
__global__ void __launch_bounds__(256) edge_fused_k(
    const int* __restrict__ ei, const float* __restrict__ ea,
    const float* __restrict__ We, const float* __restrict__ be)
{
    __shared__ float sWe[EDd * Dd];
    __shared__ float sbe[Dd];
    for (int i = threadIdx.x; i < EDd * Dd; i += 256) sWe[i] = We[i];
    for (int i = threadIdx.x; i < Dd; i += 256) sbe[i] = be[i];
    __syncthreads();
    const int warp = threadIdx.x >> 5, lane = threadIdx.x & 31;
    const int ch = lane * 4;
    const int h = lane >> 2;
    const int stride = gridDim.x * 8;

    for (int eid = blockIdx.x * 8 + warp; eid < Ee; eid += stride) {
        int src = ei[eid], dst = ei[Ee + eid];
        float eav = (lane < EDd) ? ea[(size_t)eid * EDd + lane] : 0.f;
        float e0 = sbe[ch], e1 = sbe[ch + 1], e2 = sbe[ch + 2], e3 = sbe[ch + 3];
#pragma unroll
        for (int t = 0; t < EDd; t++) {
            float a = __shfl_sync(0xffffffffu, eav, t);
            e0 += a * sWe[t * Dd + ch + 0];
            e1 += a * sWe[t * Dd + ch + 1];
            e2 += a * sWe[t * Dd + ch + 2];
            e3 += a * sWe[t * Dd + ch + 3];
        }
        float4 qd = *(const float4*)&g_qkvs[(size_t)dst * 512 + ch];
        float4 kv = *(const float4*)&g_qkvs[(size_t)src * 512 + 128 + ch];
        float p = qd.x * (kv.x + e0) + qd.y * (kv.y + e1) +
                  qd.z * (kv.z + e2) + qd.w * (kv.w + e3);
        p += __shfl_xor_sync(0xffffffffu, p, 1);
        p += __shfl_xor_sync(0xffffffffu, p, 2);
        float ex = __expf(p * 0.25f);          // SCALE = 1/sqrt(16); no max needed
        if ((lane & 3) == 0) atomicAdd(&g_den[dst * Hh + h], ex);
        float4 vs = *(const float4*)&g_qkvs[(size_t)src * 512 + 256 + ch];
        float m0 = (vs.x + e0) * ex, m1 = (vs.y + e1) * ex;
        float m2 = (vs.z + e2) * ex, m3 = (vs.w + e3) * ex;
        float* dp = &g_agg[(size_t)dst * Dd + ch];
        asm volatile("red.global.add.v4.f32 [%0], {%1,%2,%3,%4};"
                     :: "l"(dp), "f"(m0), "f"(m1), "f"(m2), "f"(m3) : "memory");
    }
}

// ---------------- node: normalize agg, beta gate, residual, LN1 (+ split h) -------
__global__ void __launch_bounds__(256) node_gate_ln1_k(
    const float* __restrict__ wb, const float* __restrict__ g1,
    const float* __restrict__ b1)
{
    int warp = threadIdx.x >> 5, lane = threadIdx.x & 31;
    int n = blockIdx.x * 8 + warp;
    if (n >= Nn) return;
    int ch = lane * 4;
    float4 ag = *(const float4*)&g_agg[(size_t)n * Dd + ch];
    float den = g_den[n * Hh + (lane >> 2)] + 1e-16f;
    float inv = 1.f / den;
    ag.x *= inv; ag.y *= inv; ag.z *= inv; ag.w *= inv;
    float4 xr = *(const float4*)&g_qkvs[(size_t)n * 512 + 384 + ch];
    float s =
        ag.x * wb[ch] + ag.y * wb[ch + 1] + ag.z * wb[ch + 2] + ag.w * wb[ch + 3] +
        xr.x * wb[128 + ch] + xr.y * wb[128 + ch + 1] + xr.z * wb[128 + ch + 2] + xr.w * wb[128 + ch + 3] +
        (ag.x - xr.x) * wb[256 + ch] + (ag.y - xr.y) * wb[256 + ch + 1] +
        (ag.z - xr.z) * wb[256 + ch + 2] + (ag.w - xr.w) * wb[256 + ch + 3];
#pragma unroll
    for (int o = 16; o; o >>= 1) s += __shfl_xor_sync(0xffffffffu, s, o);
    float beta = 1.f / (1.f + expf(-s));
    float4 hp = *(const float4*)&g_h[(size_t)n * Dd + ch];
    float t0 = beta * xr.x + (1.f - beta) * ag.x + hp.x;
    float t1 = beta * xr.y + (1.f - beta) * ag.y + hp.y;
    float t2 = beta * xr.z + (1.f - beta) * ag.z + hp.z;
    float t3 = beta * xr.w + (1.f - beta) * ag.w + hp.w;
    float sm = t0 + t1 + t2 + t3;
    float sq = t0 * t0 + t1 * t1 + t2 * t2 + t3 * t3;
#pragma unroll
    for (int o = 16; o; o >>= 1) {
        sm += __shfl_xor_sync(0xffffffffu, sm, o);
        sq += __shfl_xor_sync(0xffffffffu, sq, o);
    }
    float mu = sm * (1.f / 128.f);
    float var = sq * (1.f / 128.f) - mu * mu;
    float rs = rsqrtf(var + 1e-5f);
    float4 o4;
    o4.x = (t0 - mu) * rs * g1[ch]     + b1[ch];
    o4.y = (t1 - mu) * rs * g1[ch + 1] + b1[ch + 1];
    o4.z = (t2 - mu) * rs * g1[ch + 2] + b1[ch + 2];
    o4.w = (t3 - mu) * rs * g1[ch + 3] + b1[ch + 3];
    *(float4*)&g_h[(size_t)n * Dd + ch] = o4;
    uint32_t h0, l0, h1, l1;
    split2(o4.x, o4.y, h0, l0);
    split2(o4.z, o4.w, h1, l1);
    *(uint2*)&g_Ath[(size_t)n * Dd + ch] = make_uint2(h0, h1);
    *(uint2*)&g_Atl[(size_t)n * Dd + ch] = make_uint2(l0, l1);
}

// ---------------- node: h = LN(ff2_out + h) (+ split h) ----------------
__global__ void __launch_bounds__(256) add_ln_k(
    const float* __restrict__ g2, const float* __restrict__ b2)
{
    int warp = threadIdx.x >> 5, lane = threadIdx.x & 31;
    int n = blockIdx.x * 8 + warp;
    if (n >= Nn) return;
    int ch = lane * 4;
    float4 f  = *(const float4*)&g_agg[(size_t)n * Dd + ch];
    float4 hp = *(const float4*)&g_h[(size_t)n * Dd + ch];
    float t0 = f.x + hp.x, t1 = f.y + hp.y, t2 = f.z + hp.z, t3 = f.w + hp.w;
    float sm = t0 + t1 + t2 + t3;
    float sq = t0 * t0 + t1 * t1 + t2 * t2 + t3 * t3;
#pragma unroll
    for (int o = 16; o; o >>= 1) {
        sm += __shfl_xor_sync(0xffffffffu, sm, o);
        sq += __shfl_xor_sync(0xffffffffu, sq, o);
    }
    float mu = sm * (1.f / 128.f);
    float var = sq * (1.f / 128.f) - mu * mu;
    float rs = rsqrtf(var + 1e-5f);
    float4 o4;
    o4.x = (t0 - mu) * rs * g2[ch]     + b2[ch];
    o4.y = (t1 - mu) * rs * g2[ch + 1] + b2[ch + 1];
    o4.z = (t2 - mu) * rs * g2[ch + 2] + b2[ch + 2];
    o4.w = (t3 - mu) * rs * g2[ch + 3] + b2[ch + 3];
    *(float4*)&g_h[(size_t)n * Dd + ch] = o4;
    uint32_t h0, l0, h1, l1;
    split2(o4.x, o4.y, h0, l0);
    split2(o4.z, o4.w, h1, l1);
    *(uint2*)&g_Ath[(size_t)n * Dd + ch] = make_uint2(h0, h1);
    *(uint2*)&g_Atl[(size_t)n * Dd + ch] = make_uint2(l0, l1);
}

// ---------------- pooling ----------------
__global__ void zero_pool_k() {
    int i = blockIdx.x * blockDim.x + threadIdx.x;
    int st = gridDim.x * blockDim.x;
    for (int j = i; j < Bb * Dd; j += st) g_pool[j] = 0.f;
    for (int j = i; j < Bb; j += st) g_cnt[j] = 0.f;
}

__global__ void __launch_bounds__(256) pool_k(const int* __restrict__ batch) {
    int warp = threadIdx.x >> 5, lane = threadIdx.x & 31;
    int n = blockIdx.x * 8 + warp;
    if (n >= Nn) return;
    int b = batch[n];
    int ch = lane * 4;
    float4 h4 = *(const float4*)&g_h[(size_t)n * Dd + ch];
    float* dp = &g_pool[(size_t)b * Dd + ch];
    asm volatile("red.global.add.v4.f32 [%0], {%1,%2,%3,%4};"
                 :: "l"(dp), "f"(h4.x), "f"(h4.y), "f"(h4.z), "f"(h4.w) : "memory");
    if (lane == 0) atomicAdd(&g_cnt[b], 1.f);
}

__global__ void __launch_bounds__(256) pool_div_k() {
    int warp = threadIdx.x >> 5, lane = threadIdx.x & 31;
    int b = blockIdx.x * 8 + warp;
    if (b >= Bb) return;
    float c = fmaxf(g_cnt[b], 1.f);
    int ch = lane * 4;
    float4 p = *(const float4*)&g_pool[(size_t)b * Dd + ch];
    p.x /= c; p.y /= c; p.z /= c; p.w /= c;
    *(float4*)&g_pool[(size_t)b * Dd + ch] = p;
}

// ---------------- host ----------------
extern "C" void kernel_launch(void* const* d_in, const int* in_sizes, int n_in,
                              void* d_out, int out_size)
{
    (void)in_sizes; (void)n_in; (void)out_size;
    const float* x     = (const float*)d_in[0];
    const float* ea    = (const float*)d_in[1];
    const int*   ei    = (const int*)  d_in[2];
    const int*   batch = (const int*)  d_in[3];
    const float* Wemb  = (const float*)d_in[4];
    const float* bemb  = (const float*)d_in[5];
    const float* Wout  = (const float*)d_in[6];
    const float* bout  = (const float*)d_in[7];
    const float* Wq = (const float*)d_in[8];  const float* bq = (const float*)d_in[9];
    const float* Wk = (const float*)d_in[10]; const float* bk = (const float*)d_in[11];
    const float* Wv = (const float*)d_in[12]; const float* bv = (const float*)d_in[13];
    const float* We = (const float*)d_in[14]; const float* be = (const float*)d_in[15];
    const float* Ws = (const float*)d_in[16]; const float* bs = (const float*)d_in[17];
    const float* Wbeta = (const float*)d_in[18];
    const float* g1 = (const float*)d_in[19]; const float* b1 = (const float*)d_in[20];
    const float* g2 = (const float*)d_in[21]; const float* b2 = (const float*)d_in[22];
    const float* Wf1 = (const float*)d_in[23]; const float* bf1 = (const float*)d_in[24];
    const float* Wf2 = (const float*)d_in[25]; const float* bf2 = (const float*)d_in[26];
    float* out = (float*)d_out;

    float *p_h, *p_qkvs, *p_agg, *p_packb, *p_pool;
    ushort_t *p_Bth, *p_Btl, *p_Ath, *p_Atl, *p_Fth, *p_Ftl;
    cudaGetSymbolAddress((void**)&p_h,     g_h);
    cudaGetSymbolAddress((void**)&p_qkvs,  g_qkvs);
    cudaGetSymbolAddress((void**)&p_agg,   g_agg);
    cudaGetSymbolAddress((void**)&p_packb, g_packb);
    cudaGetSymbolAddress((void**)&p_pool,  g_pool);
    cudaGetSymbolAddress((void**)&p_Bth,   g_Bth);
    cudaGetSymbolAddress((void**)&p_Btl,   g_Btl);
    cudaGetSymbolAddress((void**)&p_Ath,   g_Ath);
    cudaGetSymbolAddress((void**)&p_Atl,   g_Atl);
    cudaGetSymbolAddress((void**)&p_Fth,   g_Fth);
    cudaGetSymbolAddress((void**)&p_Ftl,   g_Ftl);

    cudaFuncSetAttribute(gemm2_k<0>, cudaFuncAttributeMaxDynamicSharedMemorySize, SMEM_G2);
    cudaFuncSetAttribute(gemm2_k<1>, cudaFuncAttributeMaxDynamicSharedMemorySize, SMEM_G2);
    cudaFuncSetAttribute(gemm2_k<2>, cudaFuncAttributeMaxDynamicSharedMemorySize, SMEM_G2);

    dim3 blk(256);
    const int mt = (Nn + 127) / 128;          // 391
    const int ng = (Nn + 7) / 8;

    // embed: h = x @ Wemb + bemb  (fp32 + split)
    split_a_k<<<(Nn * Dd + 255) / 256, blk>>>(x, FA, Nn);
    prep_b_k<<<(Dd * Dd + 255) / 256, blk>>>(Wemb, FA, Dd, 0);
    gemm2_k<2><<<dim3(mt, 1), blk, SMEM_G2>>>(p_Ath, p_Atl, Dd, Nn, 2, p_Bth, p_Btl,
                                              bemb, p_h, nullptr, nullptr, Dd, 0);

    for (int l = 0; l < Ll; l++) {
        prep_b_k<<<64, blk>>>(Wq + (size_t)l * Dd * Dd, Dd, Dd, 0);
        prep_b_k<<<64, blk>>>(Wk + (size_t)l * Dd * Dd, Dd, Dd, 128);
        prep_b_k<<<64, blk>>>(Wv + (size_t)l * Dd * Dd, Dd, Dd, 256);
        prep_b_k<<<64, blk>>>(Ws + (size_t)l * Dd * Dd, Dd, Dd, 384);
        pack_bias4_k<<<2, blk>>>(bq, bk, bv, bs, l);
        gemm2_k<0><<<dim3(mt, 4), blk, SMEM_G2>>>(p_Ath, p_Atl, Dd, Nn, 2, p_Bth, p_Btl,
                                                  p_packb, p_qkvs, nullptr, nullptr, 4 * Dd, 0);

        zero_layer_k<<<2048, blk>>>();
        edge_fused_k<<<2048, blk>>>(ei, ea, We + (size_t)l * EDd * Dd, be + l * Dd);
        node_gate_ln1_k<<<ng, blk>>>(Wbeta + l * 3 * Dd, g1 + l * Dd, b1 + l * Dd);

        prep_b_k<<<256, blk>>>(Wf1 + (size_t)l * Dd * DFFd, Dd, DFFd, 0);
        gemm2_k<1><<<dim3(mt, 4), blk, SMEM_G2>>>(p_Ath, p_Atl, Dd, Nn, 2, p_Bth, p_Btl,
                                                  bf1 + l * DFFd, nullptr, p_Fth, p_Ftl, DFFd, 1);

        prep_b_k<<<256, blk>>>(Wf2 + (size_t)l * DFFd * Dd, DFFd, Dd, 0);
        gemm2_k<0><<<dim3(mt, 1), blk, SMEM_G2>>>(p_Fth, p_Ftl, DFFd, Nn, 8, p_Bth, p_Btl,
                                                  bf2 + l * Dd, p_agg, nullptr, nullptr, Dd, 0);

        add_ln_k<<<ng, blk>>>(g2 + l * Dd, b2 + l * Dd);
    }

    zero_pool_k<<<256, blk>>>();
    pool_k<<<ng, blk>>>(batch);
    pool_div_k<<<(Bb + 7) / 8, blk>>>();
    split_a_k<<<(Bb * Dd + 255) / 256, blk>>>(p_pool, Dd, Bb);
    prep_b_k<<<64, blk>>>(Wout, Dd, Dd, 0);
    gemm2_k<0><<<dim3(4, 1), blk, SMEM_G2>>>(p_Ath, p_Atl, Dd, Bb, 2, p_Bth, p_Btl,
                                             bout, out, nullptr, nullptr, Dd, 0);
}